// round 2
// baseline (speedup 1.0000x reference)
#include <cuda_runtime.h>
#include <cstdint>

#define DD 64            // embedding dim
#define KK 512           // num embeddings
#define ROWS 64          // rows per CTA
#define NTHREADS 256
#define NVEC 65536       // 64*32*32

// Device scratch (no cudaMalloc allowed)
__device__ float        g_wt[KK * DD];   // W transposed [k][d] for coalesced gather
__device__ float        g_c[KK];         // |w_k|^2
__device__ double       g_sse;           // sum of (q - x)^2
__device__ unsigned int g_hist[KK];      // code histogram

__device__ __forceinline__ void fma2(unsigned long long& d,
                                     unsigned long long a,
                                     unsigned long long b,
                                     unsigned long long c) {
    asm("fma.rn.f32x2 %0, %1, %2, %3;" : "=l"(d) : "l"(a), "l"(b), "l"(c));
}

// ---------------------------------------------------------------------------
// Prep: smem-tile transpose W -> Wt, |w_k|^2, zero accumulators.
// grid = 16 blocks x 256 threads; block b owns ks [b*32, b*32+32)
// ---------------------------------------------------------------------------
__global__ void vq_prep(const float* __restrict__ w) {
    __shared__ float t[32][DD + 1];
    const int b   = blockIdx.x;
    const int tid = threadIdx.x;
    const int tx  = tid & 31;     // k-local
    const int ty  = tid >> 5;     // d-group 0..7

    // Coalesced read: 32 consecutive ks per (d) row
#pragma unroll
    for (int i = 0; i < 8; i++) {
        int d = ty * 8 + i;
        t[tx][d] = w[d * KK + b * 32 + tx];
    }
    __syncthreads();

    // Coalesced-ish write of the transpose (float4)
    {
        int kr = tid >> 3;            // 0..31
        int d0 = (tid & 7) * 8;
        float4* dst = (float4*)(g_wt + (size_t)(b * 32 + kr) * DD + d0);
        float4 v0, v1;
        v0.x = t[kr][d0 + 0]; v0.y = t[kr][d0 + 1]; v0.z = t[kr][d0 + 2]; v0.w = t[kr][d0 + 3];
        v1.x = t[kr][d0 + 4]; v1.y = t[kr][d0 + 5]; v1.z = t[kr][d0 + 6]; v1.w = t[kr][d0 + 7];
        dst[0] = v0; dst[1] = v1;
    }

    if (ty == 0) {
        float s = 0.f;
#pragma unroll
        for (int d = 0; d < DD; d++) { float v = t[tx][d]; s += v * v; }
        g_c[b * 32 + tx]    = s;
        g_hist[b * 32 + tx] = 0u;
    }
    if (b == 0 && tid == 0) g_sse = 0.0;
}

// ---------------------------------------------------------------------------
// Main: whole W resident in smem (128 KB) + 64-row X tile (16 KB), occ 1.
// Per thread: 8 rows x 16 ks (4 groups of 4 contiguous ks at +0/+128/+256/+384).
// Conflict-free LDS.128 on W (lane stride 16B), broadcast LDS.32 on X.
// ---------------------------------------------------------------------------
__global__ __launch_bounds__(NTHREADS, 1)
void vq_main(const float* __restrict__ x, const float* __restrict__ w,
             float* __restrict__ out_q, float* __restrict__ out_idx) {
    extern __shared__ float sm[];
    float* ws = sm;                 // [DD][KK]  64*512 floats = 128 KB
    float* xs = sm + DD * KK;       // [ROWS][DD] 16 KB

    const int tid  = threadIdx.x;
    const int warp = tid >> 5;      // 0..7 -> rows warp*8..+7
    const int lane = tid & 31;      // k base: g*128 + lane*4
    const int rowBase = blockIdx.x * ROWS;

    // Load full W (straight copy, k-contiguous rows preserved)
    {
        float4* ws4 = (float4*)ws;
        const float4* win = (const float4*)w;
#pragma unroll
        for (int i = 0; i < (DD * KK / 4) / NTHREADS; i++)   // 32 iters
            ws4[i * NTHREADS + tid] = win[i * NTHREADS + tid];
    }
    // Load X tile
    {
        const float4* xin = (const float4*)(x + (size_t)rowBase * DD);
        float4* xs4 = (float4*)xs;
#pragma unroll
        for (int i = 0; i < (ROWS * DD / 4) / NTHREADS; i++) // 4 iters
            xs4[i * NTHREADS + tid] = xin[i * NTHREADS + tid];
    }
    __syncthreads();

    // Accumulators: acc[r][2g+h] = f32x2 dots for ks (g*128+lane*4 + 2h, +2h+1)
    unsigned long long acc[8][8];
#pragma unroll
    for (int r = 0; r < 8; r++)
#pragma unroll
        for (int c = 0; c < 8; c++) acc[r][c] = 0ULL;

    const float* xrow  = xs + warp * 8 * DD;
    const float* wbase = ws + lane * 4;

#pragma unroll 2
    for (int d = 0; d < DD; d++) {
        const float* wd = wbase + d * KK;
        ulonglong2 wv0 = *(const ulonglong2*)(wd);
        ulonglong2 wv1 = *(const ulonglong2*)(wd + 128);
        ulonglong2 wv2 = *(const ulonglong2*)(wd + 256);
        ulonglong2 wv3 = *(const ulonglong2*)(wd + 384);
#pragma unroll
        for (int r = 0; r < 8; r++) {
            float xv = xrow[r * DD + d];        // warp-uniform broadcast
            unsigned long long xx;
            asm("mov.b64 %0, {%1, %1};" : "=l"(xx) : "f"(xv));
            fma2(acc[r][0], xx, wv0.x, acc[r][0]);
            fma2(acc[r][1], xx, wv0.y, acc[r][1]);
            fma2(acc[r][2], xx, wv1.x, acc[r][2]);
            fma2(acc[r][3], xx, wv1.y, acc[r][3]);
            fma2(acc[r][4], xx, wv2.x, acc[r][4]);
            fma2(acc[r][5], xx, wv2.y, acc[r][5]);
            fma2(acc[r][6], xx, wv3.x, acc[r][6]);
            fma2(acc[r][7], xx, wv3.y, acc[r][7]);
        }
    }

    // |w|^2 for this thread's 16 ks
    float cv[16];
#pragma unroll
    for (int g = 0; g < 4; g++)
#pragma unroll
        for (int j = 0; j < 4; j++)
            cv[g * 4 + j] = g_c[g * 128 + lane * 4 + j];

    // Per-row argmax of (2*dot - |w|^2); strict '>' + ascending-k processing
    // reproduces jnp.argmax first-index tie-break.
    float bestv[8];
    int   besti[8];
#pragma unroll
    for (int r = 0; r < 8; r++) {
        float bv = -3.4e38f; int bi = 0;
#pragma unroll
        for (int g = 0; g < 4; g++) {
            int kbase = g * 128 + lane * 4;
#pragma unroll
            for (int h = 0; h < 2; h++) {
                float lo, hi;
                asm("mov.b64 {%0, %1}, %2;" : "=f"(lo), "=f"(hi) : "l"(acc[r][2 * g + h]));
                float v0 = fmaf(2.f, lo, -cv[g * 4 + 2 * h]);
                float v1 = fmaf(2.f, hi, -cv[g * 4 + 2 * h + 1]);
                int kk = kbase + 2 * h;
                if (v0 > bv) { bv = v0; bi = kk; }
                if (v1 > bv) { bv = v1; bi = kk + 1; }
            }
        }
        bestv[r] = bv; besti[r] = bi;
    }

    // Warp-wide argmax per row (min index on ties)
#pragma unroll
    for (int r = 0; r < 8; r++) {
        float v = bestv[r];
        int   i = besti[r];
#pragma unroll
        for (int off = 16; off > 0; off >>= 1) {
            float v2 = __shfl_xor_sync(0xffffffffu, v, off);
            int   i2 = __shfl_xor_sync(0xffffffffu, i, off);
            if (v2 > v || (v2 == v && i2 < i)) { v = v2; i = i2; }
        }
        besti[r] = i;
    }

    // Epilogue: coalesced code gather from Wt, ST output, SSE, hist, indices
    float sse = 0.f;
#pragma unroll
    for (int r = 0; r < 8; r++) {
        const int row  = warp * 8 + r;
        const int grow = rowBase + row;
        const int kk   = besti[r];
        if (lane == 0) {
            atomicAdd(&g_hist[kk], 1u);
            out_idx[grow] = (float)kk;
        }
        float2 q  = *(const float2*)(g_wt + (size_t)kk * DD + lane * 2);
        float2 xv = *(const float2*)(xs + row * DD + lane * 2);
        float d0 = q.x - xv.x, d1 = q.y - xv.y;
        float2 st;
        st.x = xv.x + d0;                 // x + (q - x), reference rounding
        st.y = xv.y + d1;
        *(float2*)(out_q + (size_t)grow * DD + lane * 2) = st;
        sse += d0 * d0 + d1 * d1;
    }
#pragma unroll
    for (int off = 16; off > 0; off >>= 1)
        sse += __shfl_xor_sync(0xffffffffu, sse, off);
    if (lane == 0) atomicAdd(&g_sse, (double)sse);
}

// ---------------------------------------------------------------------------
// Finalize: loss + perplexity
// ---------------------------------------------------------------------------
__global__ void vq_finalize(float* __restrict__ out_tail) {
    __shared__ float red[KK];
    int t = threadIdx.x;
    float p = (float)g_hist[t] / (float)NVEC;
    red[t] = -p * logf(p + 1e-10f);
    __syncthreads();
#pragma unroll
    for (int s = KK / 2; s > 0; s >>= 1) {
        if (t < s) red[t] += red[t + s];
        __syncthreads();
    }
    if (t == 0) {
        float m = (float)(g_sse / (double)((size_t)NVEC * DD));
        out_tail[0] = m + 0.25f * m;
        out_tail[1] = expf(red[0]);
    }
}

// ---------------------------------------------------------------------------
extern "C" void kernel_launch(void* const* d_in, const int* in_sizes, int n_in,
                              void* d_out, int out_size) {
    const float* x = (const float*)d_in[0];
    const float* w = (const float*)d_in[1];
    float* out = (float*)d_out;

    const int N = in_sizes[0] / DD;            // 65536
    const size_t ND = (size_t)N * DD;

    float* out_q    = out;
    float* out_tail = out + ND;                // loss, perplexity
    float* out_idx  = out + ND + 2;

    const int smem_bytes = (DD * KK + ROWS * DD) * (int)sizeof(float);  // 144 KB
    cudaFuncSetAttribute(vq_main, cudaFuncAttributeMaxDynamicSharedMemorySize,
                         smem_bytes);

    vq_prep<<<16, NTHREADS>>>(w);
    vq_main<<<N / ROWS, NTHREADS, smem_bytes>>>(x, w, out_q, out_idx);
    vq_finalize<<<1, KK>>>(out_tail);
}

// round 3
// speedup vs baseline: 1.2713x; 1.2713x over previous
#include <cuda_runtime.h>
#include <cstdint>

#define DD 64            // embedding dim
#define KK 512           // num embeddings
#define KC 256           // K-chunk in smem
#define ROWS 64          // rows per CTA
#define NTHREADS 256
#define NVEC 65536       // 64*32*32

// Device scratch (no cudaMalloc allowed)
__device__ float        g_wt[KK * DD];   // W transposed [k][d] for coalesced gather
__device__ float        g_c[KK];         // |w_k|^2
__device__ double       g_sse;           // sum of (q - x)^2
__device__ unsigned int g_hist[KK];      // code histogram

__device__ __forceinline__ void fma2(unsigned long long& d,
                                     unsigned long long a,
                                     unsigned long long b,
                                     unsigned long long c) {
    asm("fma.rn.f32x2 %0, %1, %2, %3;" : "=l"(d) : "l"(a), "l"(b), "l"(c));
}

// ---------------------------------------------------------------------------
// Prep: smem-tile transpose W -> Wt, |w_k|^2, zero accumulators.
// grid = 16 blocks x 256 threads; block b owns ks [b*32, b*32+32)
// ---------------------------------------------------------------------------
__global__ void vq_prep(const float* __restrict__ w) {
    __shared__ float t[32][DD + 1];
    const int b   = blockIdx.x;
    const int tid = threadIdx.x;
    const int tx  = tid & 31;     // k-local
    const int ty  = tid >> 5;     // d-group 0..7

#pragma unroll
    for (int i = 0; i < 8; i++) {
        int d = ty * 8 + i;
        t[tx][d] = w[d * KK + b * 32 + tx];   // coalesced across k
    }
    __syncthreads();

    {   // transpose write (float4 pairs)
        int kr = tid >> 3;            // 0..31
        int d0 = (tid & 7) * 8;
        float4* dst = (float4*)(g_wt + (size_t)(b * 32 + kr) * DD + d0);
        float4 v0, v1;
        v0.x = t[kr][d0 + 0]; v0.y = t[kr][d0 + 1]; v0.z = t[kr][d0 + 2]; v0.w = t[kr][d0 + 3];
        v1.x = t[kr][d0 + 4]; v1.y = t[kr][d0 + 5]; v1.z = t[kr][d0 + 6]; v1.w = t[kr][d0 + 7];
        dst[0] = v0; dst[1] = v1;
    }

    if (ty == 0) {
        float s = 0.f;
#pragma unroll
        for (int d = 0; d < DD; d++) { float v = t[tx][d]; s += v * v; }
        g_c[b * 32 + tx]    = s;
        g_hist[b * 32 + tx] = 0u;
    }
    if (b == 0 && tid == 0) g_sse = 0.0;
}

// ---------------------------------------------------------------------------
// Main: K in 2 chunks of 256 via smem (occ 2). Per thread: 8 rows x 8 ks,
// ks = two groups of 4 CONTIGUOUS ks at +0/+128 (conflict-free LDS.128,
// lane stride 16B). X read as float2 broadcast, d unrolled by 2.
// ---------------------------------------------------------------------------
__global__ __launch_bounds__(NTHREADS, 2)
void vq_main(const float* __restrict__ x, const float* __restrict__ w,
             float* __restrict__ out_q, float* __restrict__ out_idx) {
    extern __shared__ float sm[];
    float* ws = sm;                       // [DD][KC] 64 KB
    float* xs = sm + DD * KC;             // [ROWS][DD] 16 KB
    float* cs = sm + DD * KC + ROWS * DD; // [KC] 1 KB

    const int tid  = threadIdx.x;
    const int warp = tid >> 5;      // rows warp*8..+7
    const int lane = tid & 31;      // ks: g*128 + lane*4 + j
    const int rowBase = blockIdx.x * ROWS;

    // Load X tile (coalesced float4)
    {
        const float4* xin = (const float4*)(x + (size_t)rowBase * DD);
        float4* xs4 = (float4*)xs;
#pragma unroll
        for (int i = 0; i < (ROWS * DD / 4) / NTHREADS; i++)
            xs4[i * NTHREADS + tid] = xin[i * NTHREADS + tid];
    }

    float bestv[8];
    int   besti[8];
#pragma unroll
    for (int r = 0; r < 8; r++) { bestv[r] = -3.4e38f; besti[r] = 0; }

#pragma unroll 1
    for (int chunk = 0; chunk < KK / KC; chunk++) {
        const int kc = chunk * KC;
        __syncthreads();               // protect ws/cs reuse
        {   // load W chunk [DD][KC] (coalesced float4) + c chunk
            float4* ws4 = (float4*)ws;
#pragma unroll
            for (int i = 0; i < (DD * KC / 4) / NTHREADS; i++) {
                int idx = i * NTHREADS + tid;    // 64 float4 per d-row
                int dd = idx >> 6, jj = idx & 63;
                ws4[idx] = *(const float4*)(w + dd * KK + kc + jj * 4);
            }
            if (tid < KC) cs[tid] = g_c[kc + tid];
        }
        __syncthreads();

        unsigned long long acc[8][4];
#pragma unroll
        for (int r = 0; r < 8; r++)
#pragma unroll
            for (int c = 0; c < 4; c++) acc[r][c] = 0ULL;

        const float* xrow  = xs + warp * 8 * DD;
        const float* wbase = ws + lane * 4;

#pragma unroll 2
        for (int d = 0; d < DD; d += 2) {
            // W vectors for two d's, two contiguous k-groups each
            const float* wd0 = wbase + d * KC;
            const float* wd1 = wd0 + KC;
            ulonglong2 w00 = *(const ulonglong2*)(wd0);        // d,   ks lane*4..+3
            ulonglong2 w01 = *(const ulonglong2*)(wd0 + 128);  // d,   ks 128+lane*4..
            ulonglong2 w10 = *(const ulonglong2*)(wd1);        // d+1
            ulonglong2 w11 = *(const ulonglong2*)(wd1 + 128);
#pragma unroll
            for (int r = 0; r < 8; r++) {
                float2 xp = *(const float2*)(xrow + r * DD + d);  // broadcast
                unsigned long long xx0, xx1;
                asm("mov.b64 %0, {%1, %1};" : "=l"(xx0) : "f"(xp.x));
                asm("mov.b64 %0, {%1, %1};" : "=l"(xx1) : "f"(xp.y));
                fma2(acc[r][0], xx0, w00.x, acc[r][0]);
                fma2(acc[r][1], xx0, w00.y, acc[r][1]);
                fma2(acc[r][2], xx0, w01.x, acc[r][2]);
                fma2(acc[r][3], xx0, w01.y, acc[r][3]);
                fma2(acc[r][0], xx1, w10.x, acc[r][0]);
                fma2(acc[r][1], xx1, w10.y, acc[r][1]);
                fma2(acc[r][2], xx1, w11.x, acc[r][2]);
                fma2(acc[r][3], xx1, w11.y, acc[r][3]);
            }
        }

        // Scores: argmax of (2*dot - |w|^2) == argmin distance; ascending k
        // + strict '>' reproduces jnp.argmax first-index tie-break.
#pragma unroll
        for (int r = 0; r < 8; r++) {
            float bv = bestv[r]; int bi = besti[r];
#pragma unroll
            for (int g = 0; g < 2; g++) {
                int kbase = g * 128 + lane * 4;
#pragma unroll
                for (int h = 0; h < 2; h++) {
                    float lo, hi;
                    asm("mov.b64 {%0, %1}, %2;" : "=f"(lo), "=f"(hi)
                        : "l"(acc[r][2 * g + h]));
                    float c0 = cs[kbase + 2 * h];
                    float c1 = cs[kbase + 2 * h + 1];
                    float v0 = fmaf(2.f, lo, -c0);
                    float v1 = fmaf(2.f, hi, -c1);
                    int kk = kc + kbase + 2 * h;
                    if (v0 > bv) { bv = v0; bi = kk; }
                    if (v1 > bv) { bv = v1; bi = kk + 1; }
                }
            }
            bestv[r] = bv; besti[r] = bi;
        }
    }

    // Warp-wide argmax per row (min index on ties)
#pragma unroll
    for (int r = 0; r < 8; r++) {
        float v = bestv[r];
        int   i = besti[r];
#pragma unroll
        for (int off = 16; off > 0; off >>= 1) {
            float v2 = __shfl_xor_sync(0xffffffffu, v, off);
            int   i2 = __shfl_xor_sync(0xffffffffu, i, off);
            if (v2 > v || (v2 == v && i2 < i)) { v = v2; i = i2; }
        }
        besti[r] = i;
    }

    // Epilogue: coalesced code gather from Wt, ST output, SSE, hist, indices
    float sse = 0.f;
#pragma unroll
    for (int r = 0; r < 8; r++) {
        const int row  = warp * 8 + r;
        const int grow = rowBase + row;
        const int kk   = besti[r];
        if (lane == 0) {
            atomicAdd(&g_hist[kk], 1u);
            out_idx[grow] = (float)kk;
        }
        float2 q  = *(const float2*)(g_wt + (size_t)kk * DD + lane * 2);
        float2 xv = *(const float2*)(xs + row * DD + lane * 2);
        float d0 = q.x - xv.x, d1 = q.y - xv.y;
        float2 st;
        st.x = xv.x + d0;                 // x + (q - x), reference rounding
        st.y = xv.y + d1;
        *(float2*)(out_q + (size_t)grow * DD + lane * 2) = st;
        sse += d0 * d0 + d1 * d1;
    }
#pragma unroll
    for (int off = 16; off > 0; off >>= 1)
        sse += __shfl_xor_sync(0xffffffffu, sse, off);
    if (lane == 0) atomicAdd(&g_sse, (double)sse);
}

// ---------------------------------------------------------------------------
// Finalize: loss + perplexity
// ---------------------------------------------------------------------------
__global__ void vq_finalize(float* __restrict__ out_tail) {
    __shared__ float red[KK];
    int t = threadIdx.x;
    float p = (float)g_hist[t] / (float)NVEC;
    red[t] = -p * logf(p + 1e-10f);
    __syncthreads();
#pragma unroll
    for (int s = KK / 2; s > 0; s >>= 1) {
        if (t < s) red[t] += red[t + s];
        __syncthreads();
    }
    if (t == 0) {
        float m = (float)(g_sse / (double)((size_t)NVEC * DD));
        out_tail[0] = m + 0.25f * m;
        out_tail[1] = expf(red[0]);
    }
}

// ---------------------------------------------------------------------------
extern "C" void kernel_launch(void* const* d_in, const int* in_sizes, int n_in,
                              void* d_out, int out_size) {
    const float* x = (const float*)d_in[0];
    const float* w = (const float*)d_in[1];
    float* out = (float*)d_out;

    const int N = in_sizes[0] / DD;            // 65536
    const size_t ND = (size_t)N * DD;

    float* out_q    = out;
    float* out_tail = out + ND;                // loss, perplexity
    float* out_idx  = out + ND + 2;

    const int smem_bytes = (DD * KC + ROWS * DD + KC) * (int)sizeof(float); // 81 KB
    cudaFuncSetAttribute(vq_main, cudaFuncAttributeMaxDynamicSharedMemorySize,
                         smem_bytes);

    vq_prep<<<16, NTHREADS>>>(w);
    vq_main<<<N / ROWS, NTHREADS, smem_bytes>>>(x, w, out_q, out_idx);
    vq_finalize<<<1, KK>>>(out_tail);
}

// round 5
// speedup vs baseline: 1.4231x; 1.1194x over previous
#include <cuda_runtime.h>
#include <cuda_bf16.h>
#include <cstdint>

#define DD    64
#define KK    512
#define ROWS  128          // x-rows per CTA
#define NT    256          // threads per CTA (8 warps)
#define NVEC  65536
#define EPS   1e-2f        // recheck window (worst-case split error ~4e-4)

// ---- gmem scratch (no cudaMalloc allowed) ----
// B fragment image: [ukt 0..7][ntile 0..63][lane 0..31][2 x b32]
// ukt 0-3 = w0 k-blocks 0-3; ukt 4-7 = w1 k-blocks 0-3
__device__ __align__(16) uint32_t g_bfrag[8 * 64 * 32 * 2];
__device__ float        g_wt[KK * DD];   // W^T [k][d] for gather + recheck
__device__ float        g_c[KK];         // |w_k|^2
__device__ double       g_sse;
__device__ unsigned int g_hist[KK];

// ---- smem layout (bytes) ----
#define OFF_CS 0                 // 512 f32      (2 KB)
#define OFF_X  2048              // 128x64 f32   (32 KB)
#define OFF_BF 34816             // b-frag image (131072 B)
#define SMEM_TOTAL 165888

static __device__ __forceinline__ uint32_t bfb(float v) {   // bf16 bits (rn)
    unsigned short s;
    asm("{.reg .b16 t; cvt.rn.bf16.f32 t, %1; mov.b16 %0, t;}" : "=h"(s) : "f"(v));
    return (uint32_t)s;
}
static __device__ __forceinline__ float unbf(uint32_t b) { return __uint_as_float(b << 16); }
static __device__ __forceinline__ uint32_t pack2(uint32_t lo, uint32_t hi) { return lo | (hi << 16); }

static __device__ __forceinline__ void hmma(float* d, const uint32_t* a,
                                            uint32_t b0, uint32_t b1) {
    asm volatile(
        "mma.sync.aligned.m16n8k16.row.col.f32.bf16.bf16.f32 "
        "{%0,%1,%2,%3}, {%4,%5,%6,%7}, {%8,%9}, {%0,%1,%2,%3};"
        : "+f"(d[0]), "+f"(d[1]), "+f"(d[2]), "+f"(d[3])
        : "r"(a[0]), "r"(a[1]), "r"(a[2]), "r"(a[3]), "r"(b0), "r"(b1));
}
static __device__ __forceinline__ void cpa16(uint32_t s, const void* g) {
    asm volatile("cp.async.cg.shared.global [%0], [%1], 16;" :: "r"(s), "l"(g));
}
#define CP_COMMIT() asm volatile("cp.async.commit_group;" ::: "memory")
#define CP_WAIT0()  asm volatile("cp.async.wait_group 0;" ::: "memory")

static __device__ __forceinline__ uint32_t smem_u32(const void* p) {
    uint32_t a;
    asm("{ .reg .u64 t; cvta.to.shared.u64 t, %1; cvt.u32.u64 %0, t; }" : "=r"(a) : "l"(p));
    return a;
}

// top-2 insert, within-lane (ascending k => strict '>' keeps first index)
static __device__ __forceinline__ void top2(float v, int k, float& v1, int& i1,
                                            float& v2, int& i2) {
    if (v > v1)      { v2 = v1; i2 = i1; v1 = v; i1 = k; }
    else if (v > v2) { v2 = v;  i2 = k; }
}
// top-2 insert with first-index tie rule (cross-lane merge)
static __device__ __forceinline__ void top2t(float v, int k, float& v1, int& i1,
                                             float& v2, int& i2) {
    if (v > v1 || (v == v1 && k < i1))      { v2 = v1; i2 = i1; v1 = v; i1 = k; }
    else if (v > v2 || (v == v2 && k < i2)) { v2 = v;  i2 = k; }
}

// ---------------------------------------------------------------------------
// Prep: W^T + |w|^2 + zeros + B-fragment image (bf16 splits, HMMA reg layout)
// grid = 16 x 256; block b owns codes [b*32, b*32+32)
// ---------------------------------------------------------------------------
__global__ void vq_prep(const float* __restrict__ w) {
    __shared__ float t[32][DD + 1];
    const int b = blockIdx.x, tid = threadIdx.x;
    const int tx = tid & 31, ty = tid >> 5;

#pragma unroll
    for (int i = 0; i < 8; i++) {
        int d = ty * 8 + i;
        t[tx][d] = w[d * KK + b * 32 + tx];      // coalesced across k
    }
    __syncthreads();

    {   // W^T write
        int kr = tid >> 3;                       // 0..31
        int d0 = (tid & 7) * 8;
        float4* dst = (float4*)(g_wt + (size_t)(b * 32 + kr) * DD + d0);
        float4 v0, v1;
        v0.x = t[kr][d0 + 0]; v0.y = t[kr][d0 + 1]; v0.z = t[kr][d0 + 2]; v0.w = t[kr][d0 + 3];
        v1.x = t[kr][d0 + 4]; v1.y = t[kr][d0 + 5]; v1.z = t[kr][d0 + 6]; v1.w = t[kr][d0 + 7];
        dst[0] = v0; dst[1] = v1;
    }

    if (ty == 0) {
        float s = 0.f;
#pragma unroll
        for (int d = 0; d < DD; d++) { float v = t[tx][d]; s += v * v; }
        g_c[b * 32 + tx]    = s;
        g_hist[b * 32 + tx] = 0u;
    }
    if (b == 0 && tid == 0) g_sse = 0.0;

    // B fragment image: thread = (ukt, lane); loop 4 local ntiles
    {
        const int u    = tid >> 5;               // 0..7
        const int lane = tid & 31;
        const int seg  = u >> 2;                 // 0 = w0, 1 = w1
        const int kblk = u & 3;
#pragma unroll
        for (int ntl = 0; ntl < 4; ntl++) {
            int nt = b * 4 + ntl;
            int n  = nt * 8 + (lane >> 2);       // global code
#pragma unroll
            for (int j2 = 0; j2 < 2; j2++) {
                int k0 = kblk * 16 + (lane & 3) * 2 + j2 * 8;  // d index
                float v0 = w[k0 * KK + n];
                float v1 = w[(k0 + 1) * KK + n];
                uint32_t lo, hi;
                if (seg == 0) { lo = bfb(v0); hi = bfb(v1); }
                else {
                    lo = bfb(v0 - unbf(bfb(v0)));
                    hi = bfb(v1 - unbf(bfb(v1)));
                }
                g_bfrag[((u * 64 + nt) * 32 + lane) * 2 + j2] = pack2(lo, hi);
            }
        }
    }
}

// ---------------------------------------------------------------------------
// Main: 512 CTAs x 256 thr. bf16 3-split HMMA GEMM (K_ext=192, 8 unique
// k-tiles), top-2 argmax + exact fp32 recheck in the EPS window.
// ---------------------------------------------------------------------------
__global__ __launch_bounds__(NT)
void vq_main(const float* __restrict__ x,
             float* __restrict__ out_q, float* __restrict__ out_idx) {
    extern __shared__ unsigned char sm[];
    const uint32_t smb = smem_u32(sm);
    float* cs = (float*)(sm + OFF_CS);
    float* xs = (float*)(sm + OFF_X);
    const uint2* bfr = (const uint2*)(sm + OFF_BF);

    const int tid  = threadIdx.x;
    const int warp = tid >> 5, lane = tid & 31;
    const int rowBase = blockIdx.x * ROWS;

    // cp.async: b-frag image (131 KB) + x tile (32 KB) + |w|^2 (2 KB)
    {
        const unsigned char* gb = (const unsigned char*)g_bfrag;
#pragma unroll
        for (int i = 0; i < 32; i++) {
            int idx = i * NT + tid;
            cpa16(smb + OFF_BF + idx * 16, gb + idx * 16);
        }
        const unsigned char* xg = (const unsigned char*)(x + (size_t)rowBase * DD);
#pragma unroll
        for (int i = 0; i < 8; i++) {
            int idx = i * NT + tid;
            cpa16(smb + OFF_X + idx * 16, xg + idx * 16);
        }
        if (tid < 128) cpa16(smb + OFF_CS + tid * 16, (const unsigned char*)g_c + tid * 16);
        CP_COMMIT();
        CP_WAIT0();
    }
    __syncthreads();

    // Build A fragments in registers: ax0 (bf16 main), ax1 (bf16 residual)
    const int r0 = warp * 16 + (lane >> 2);
    const int r1 = r0 + 8;
    uint32_t ax0[4][4], ax1[4][4];
#pragma unroll
    for (int u = 0; u < 4; u++) {
        int kb = u * 16 + (lane & 3) * 2;
        float p00 = xs[r0 * DD + kb],     p01 = xs[r0 * DD + kb + 1];
        float p10 = xs[r1 * DD + kb],     p11 = xs[r1 * DD + kb + 1];
        float q00 = xs[r0 * DD + kb + 8], q01 = xs[r0 * DD + kb + 9];
        float q10 = xs[r1 * DD + kb + 8], q11 = xs[r1 * DD + kb + 9];
        uint32_t b00 = bfb(p00), b01 = bfb(p01), b10 = bfb(p10), b11 = bfb(p11);
        uint32_t c00 = bfb(q00), c01 = bfb(q01), c10 = bfb(q10), c11 = bfb(q11);
        ax0[u][0] = pack2(b00, b01);
        ax0[u][1] = pack2(b10, b11);
        ax0[u][2] = pack2(c00, c01);
        ax0[u][3] = pack2(c10, c11);
        ax1[u][0] = pack2(bfb(p00 - unbf(b00)), bfb(p01 - unbf(b01)));
        ax1[u][1] = pack2(bfb(p10 - unbf(b10)), bfb(p11 - unbf(b11)));
        ax1[u][2] = pack2(bfb(q00 - unbf(c00)), bfb(q01 - unbf(c01)));
        ax1[u][3] = pack2(bfb(q10 - unbf(c10)), bfb(q11 - unbf(c11)));
    }

    // Top-2 per owned row (r0 in set a, r1 in set b)
    float v1a = -3.4e38f, v2a = -3.4e38f, v1b = -3.4e38f, v2b = -3.4e38f;
    int   i1a = 0, i2a = 0, i1b = 0, i2b = 0;

#pragma unroll 1
    for (int chunk = 0; chunk < 4; chunk++) {
        float dacc[16][4];
#pragma unroll
        for (int nt = 0; nt < 16; nt++)
#pragma unroll
            for (int j = 0; j < 4; j++) dacc[nt][j] = 0.f;

        // K loop: kt 0-3 x0*w0, 4-7 x1*w0, 8-11 x0*w1
#pragma unroll
        for (int kt = 0; kt < 12; kt++) {
            const uint32_t* A = (kt < 4) ? ax0[kt] : (kt < 8) ? ax1[kt - 4] : ax0[kt - 8];
            const int ukt = (kt < 8) ? (kt & 3) : 4 + (kt - 8);
            const uint2* bp = bfr + ((ukt * 64 + chunk * 16) * 32 + lane);
#pragma unroll
            for (int nt = 0; nt < 16; nt++) {
                uint2 bb = bp[nt * 32];
                hmma(dacc[nt], A, bb.x, bb.y);
            }
        }

        // Scores + top-2 (ascending k within lane)
#pragma unroll
        for (int nt = 0; nt < 16; nt++) {
            int c0 = chunk * 128 + nt * 8 + (lane & 3) * 2;
            float cc0 = cs[c0], cc1 = cs[c0 + 1];
            top2(fmaf(2.f, dacc[nt][0], -cc0), c0,     v1a, i1a, v2a, i2a);
            top2(fmaf(2.f, dacc[nt][1], -cc1), c0 + 1, v1a, i1a, v2a, i2a);
            top2(fmaf(2.f, dacc[nt][2], -cc0), c0,     v1b, i1b, v2b, i2b);
            top2(fmaf(2.f, dacc[nt][3], -cc1), c0 + 1, v1b, i1b, v2b, i2b);
        }
    }

    // Merge across the 4 lanes of the quad (same rows)
#pragma unroll
    for (int off = 1; off <= 2; off <<= 1) {
        float mv1 = __shfl_xor_sync(0xffffffffu, v1a, off);
        int   mi1 = __shfl_xor_sync(0xffffffffu, i1a, off);
        float mv2 = __shfl_xor_sync(0xffffffffu, v2a, off);
        int   mi2 = __shfl_xor_sync(0xffffffffu, i2a, off);
        top2t(mv1, mi1, v1a, i1a, v2a, i2a);
        top2t(mv2, mi2, v1a, i1a, v2a, i2a);
        mv1 = __shfl_xor_sync(0xffffffffu, v1b, off);
        mi1 = __shfl_xor_sync(0xffffffffu, i1b, off);
        mv2 = __shfl_xor_sync(0xffffffffu, v2b, off);
        mi2 = __shfl_xor_sync(0xffffffffu, i2b, off);
        top2t(mv1, mi1, v1b, i1b, v2b, i2b);
        top2t(mv2, mi2, v1b, i1b, v2b, i2b);
    }

    // Owner lanes: exact fp32 recheck in EPS window, then idx + hist
    if ((lane & 3) == 0) {
        if (v1a - v2a < EPS) {
            float s1 = 0.f, s2 = 0.f;
            const float* w1p = g_wt + (size_t)i1a * DD;
            const float* w2p = g_wt + (size_t)i2a * DD;
#pragma unroll 4
            for (int d = 0; d < DD; d++) {
                float xv = xs[r0 * DD + d];
                s1 = fmaf(xv, w1p[d], s1);
                s2 = fmaf(xv, w2p[d], s2);
            }
            s1 = 2.f * s1 - cs[i1a];
            s2 = 2.f * s2 - cs[i2a];
            if (s2 > s1 || (s2 == s1 && i2a < i1a)) i1a = i2a;
        }
        if (v1b - v2b < EPS) {
            float s1 = 0.f, s2 = 0.f;
            const float* w1p = g_wt + (size_t)i1b * DD;
            const float* w2p = g_wt + (size_t)i2b * DD;
#pragma unroll 4
            for (int d = 0; d < DD; d++) {
                float xv = xs[r1 * DD + d];
                s1 = fmaf(xv, w1p[d], s1);
                s2 = fmaf(xv, w2p[d], s2);
            }
            s1 = 2.f * s1 - cs[i1b];
            s2 = 2.f * s2 - cs[i2b];
            if (s2 > s1 || (s2 == s1 && i2b < i1b)) i1b = i2b;
        }
        out_idx[rowBase + r0] = (float)i1a;
        out_idx[rowBase + r1] = (float)i1b;
        atomicAdd(&g_hist[i1a], 1u);
        atomicAdd(&g_hist[i1b], 1u);
    }

    // Gather/ST/SSE epilogue: warp handles its 16 rows, lanes = dims
    float sse = 0.f;
#pragma unroll 1
    for (int i = 0; i < 16; i++) {
        int bsel = (i < 8) ? i1a : i1b;
        int bir  = __shfl_sync(0xffffffffu, bsel, (i & 7) << 2);
        int rowl = warp * 16 + i;
        float2 q  = *(const float2*)(g_wt + (size_t)bir * DD + lane * 2);
        float2 xv = *(const float2*)(xs + rowl * DD + lane * 2);
        float d0 = q.x - xv.x, d1 = q.y - xv.y;
        float2 st;
        st.x = xv.x + d0;                 // x + (q - x), reference rounding
        st.y = xv.y + d1;
        *(float2*)(out_q + (size_t)(rowBase + rowl) * DD + lane * 2) = st;
        sse += d0 * d0 + d1 * d1;
    }
#pragma unroll
    for (int off = 16; off > 0; off >>= 1)
        sse += __shfl_xor_sync(0xffffffffu, sse, off);
    if (lane == 0) atomicAdd(&g_sse, (double)sse);
}

// ---------------------------------------------------------------------------
// Finalize: loss + perplexity
// ---------------------------------------------------------------------------
__global__ void vq_finalize(float* __restrict__ out_tail) {
    __shared__ float red[KK];
    int t = threadIdx.x;
    float p = (float)g_hist[t] / (float)NVEC;
    red[t] = -p * logf(p + 1e-10f);
    __syncthreads();
#pragma unroll
    for (int s = KK / 2; s > 0; s >>= 1) {
        if (t < s) red[t] += red[t + s];
        __syncthreads();
    }
    if (t == 0) {
        float m = (float)(g_sse / (double)((size_t)NVEC * DD));
        out_tail[0] = m + 0.25f * m;
        out_tail[1] = expf(red[0]);
    }
}

// ---------------------------------------------------------------------------
extern "C" void kernel_launch(void* const* d_in, const int* in_sizes, int n_in,
                              void* d_out, int out_size) {
    const float* x = (const float*)d_in[0];
    const float* w = (const float*)d_in[1];
    float* out = (float*)d_out;

    const int N = in_sizes[0] / DD;            // 65536
    const size_t ND = (size_t)N * DD;

    float* out_q    = out;
    float* out_tail = out + ND;                // loss, perplexity
    float* out_idx  = out + ND + 2;

    cudaFuncSetAttribute(vq_main, cudaFuncAttributeMaxDynamicSharedMemorySize,
                         SMEM_TOTAL);

    vq_prep<<<16, 256>>>(w);
    vq_main<<<N / ROWS, NT, SMEM_TOTAL>>>(x, out_q, out_idx);
    vq_finalize<<<1, KK>>>(out_tail);
}

// round 6
// speedup vs baseline: 1.5677x; 1.1017x over previous
#include <cuda_runtime.h>
#include <cuda_fp16.h>
#include <cstdint>

#define DD    64
#define KK    512
#define ROWS  128          // x-rows per CTA
#define NT    256          // 8 warps
#define NVEC  65536
#define EPS   0.03f        // > 2x worst-case fp16 single-product score error

// ---- gmem scratch (no cudaMalloc allowed) ----
// B fragment image: [kt 0..3][ntp 0..31][lane 0..31] uint4
//   uint4 = {nt_even.b0, nt_even.b1, nt_odd.b0, nt_odd.b1} (fp16x2 each)
__device__ __align__(16) uint4 g_bfrag4[4 * 32 * 32];
__device__ float        g_wt[KK * DD];   // W^T [k][d] for gather
__device__ float        g_c[KK];         // |w_k|^2
__device__ double       g_sse;
__device__ unsigned int g_hist[KK];

// ---- smem layout (bytes) ----
#define OFF_CS    0        // 512 f32 (2048)
#define OFF_IDX   2048     // int s_idx[128] (512)
#define OFF_NFLAG 2560     // int (4)
#define OFF_FROW  2564     // int[128] (512)
#define OFF_FBV   3080     // float[128]
#define OFF_FBI   3592     // int[128]
#define OFF_X     4608     // 128x64 f32 (32768)
#define OFF_BF    37376    // 64 KB: B frags; later reused as W fp32 [64][256]
#define SMEM_TOTAL 102912

static __device__ __forceinline__ uint32_t h2(float lo, float hi) {
    __half2 h = __floats2half2_rn(lo, hi);          // .x = low 16 bits
    return *(uint32_t*)&h;
}
static __device__ __forceinline__ void hmma(float* d, const uint32_t* a,
                                            uint32_t b0, uint32_t b1) {
    asm volatile(
        "mma.sync.aligned.m16n8k16.row.col.f32.f16.f16.f32 "
        "{%0,%1,%2,%3}, {%4,%5,%6,%7}, {%8,%9}, {%0,%1,%2,%3};"
        : "+f"(d[0]), "+f"(d[1]), "+f"(d[2]), "+f"(d[3])
        : "r"(a[0]), "r"(a[1]), "r"(a[2]), "r"(a[3]), "r"(b0), "r"(b1));
}
static __device__ __forceinline__ void cpa16(uint32_t s, const void* g) {
    asm volatile("cp.async.cg.shared.global [%0], [%1], 16;" :: "r"(s), "l"(g));
}
#define CP_COMMIT() asm volatile("cp.async.commit_group;" ::: "memory")
#define CP_WAIT0()  asm volatile("cp.async.wait_group 0;" ::: "memory")

static __device__ __forceinline__ uint32_t smem_u32(const void* p) {
    uint32_t a;
    asm("{ .reg .u64 t; cvta.to.shared.u64 t, %1; cvt.u32.u64 %0, t; }" : "=r"(a) : "l"(p));
    return a;
}

// top-1 + runner-up value; first-index tie rule on v1
static __device__ __forceinline__ void t2(float v, int k, float& v1, int& i1, float& v2) {
    if (v > v1 || (v == v1 && k < i1)) { v2 = v1; v1 = v; i1 = k; }
    else if (v > v2) v2 = v;
}

// ---------------------------------------------------------------------------
// Prep: W^T + |w|^2 + zeros + fp16 B-fragment image
// grid = 16 x 256; block b owns codes [b*32, b*32+32)
// ---------------------------------------------------------------------------
__global__ void vq_prep(const float* __restrict__ w) {
    __shared__ float t[32][DD + 1];
    const int b = blockIdx.x, tid = threadIdx.x;
    const int tx = tid & 31, ty = tid >> 5;

#pragma unroll
    for (int i = 0; i < 8; i++) {
        int d = ty * 8 + i;
        t[tx][d] = w[d * KK + b * 32 + tx];      // coalesced across k
    }
    __syncthreads();

    {   // W^T write
        int kr = tid >> 3;
        int d0 = (tid & 7) * 8;
        float4* dst = (float4*)(g_wt + (size_t)(b * 32 + kr) * DD + d0);
        float4 v0, v1;
        v0.x = t[kr][d0 + 0]; v0.y = t[kr][d0 + 1]; v0.z = t[kr][d0 + 2]; v0.w = t[kr][d0 + 3];
        v1.x = t[kr][d0 + 4]; v1.y = t[kr][d0 + 5]; v1.z = t[kr][d0 + 6]; v1.w = t[kr][d0 + 7];
        dst[0] = v0; dst[1] = v1;
    }

    if (ty == 0) {
        float s = 0.f;
#pragma unroll
        for (int d = 0; d < DD; d++) { float v = t[tx][d]; s += v * v; }
        g_c[b * 32 + tx]    = s;
        g_hist[b * 32 + tx] = 0u;
    }
    if (b == 0 && tid == 0) g_sse = 0.0;

    // B fragment image: thread = (kblk, half, lane)
    {
        const int kblk = (tid >> 5) & 3;
        const int half = tid >> 7;
        const int lane = tid & 31;
        const int ntp  = b * 2 + half;
        uint32_t q[4];
#pragma unroll
        for (int hh = 0; hh < 2; hh++) {
            int nt = ntp * 2 + hh;
            int n  = nt * 8 + (lane >> 2);
#pragma unroll
            for (int j2 = 0; j2 < 2; j2++) {
                int k0 = kblk * 16 + (lane & 3) * 2 + j2 * 8;
                q[hh * 2 + j2] = h2(w[k0 * KK + n], w[(k0 + 1) * KK + n]);
            }
        }
        g_bfrag4[(kblk * 32 + ntp) * 32 + lane] = make_uint4(q[0], q[1], q[2], q[3]);
    }
}

// ---------------------------------------------------------------------------
// Main: fp16 single-product HMMA coarse scores (K=64, 4 kt), gap test,
// exact fp32 full-scan fallback for near-ties (guaranteed-correct argmax).
// ---------------------------------------------------------------------------
__global__ __launch_bounds__(NT, 2)
void vq_main(const float* __restrict__ x, const float* __restrict__ w,
             float* __restrict__ out_q, float* __restrict__ out_idx) {
    extern __shared__ unsigned char sm[];
    const uint32_t smb = smem_u32(sm);
    float* cs = (float*)(sm + OFF_CS);
    float* xs = (float*)(sm + OFF_X);
    int*   s_idx   = (int*)(sm + OFF_IDX);
    int*   s_nflag = (int*)(sm + OFF_NFLAG);
    int*   s_frow  = (int*)(sm + OFF_FROW);
    float* s_fbv   = (float*)(sm + OFF_FBV);
    int*   s_fbi   = (int*)(sm + OFF_FBI);
    const uint4* bfr4 = (const uint4*)(sm + OFF_BF);
    float* wf = (float*)(sm + OFF_BF);       // fallback W slab (reuses BF)

    const int tid  = threadIdx.x;
    const int warp = tid >> 5, lane = tid & 31;
    const int rowBase = blockIdx.x * ROWS;

    if (tid == 0) *s_nflag = 0;

    // cp.async: B-frag image (64 KB) + x tile (32 KB) + |w|^2 (2 KB)
    {
        const unsigned char* gb = (const unsigned char*)g_bfrag4;
#pragma unroll
        for (int i = 0; i < 16; i++) {
            int idx = i * NT + tid;
            cpa16(smb + OFF_BF + idx * 16, gb + idx * 16);
        }
        const unsigned char* xg = (const unsigned char*)(x + (size_t)rowBase * DD);
#pragma unroll
        for (int i = 0; i < 8; i++) {
            int idx = i * NT + tid;
            cpa16(smb + OFF_X + idx * 16, xg + idx * 16);
        }
        if (tid < 128) cpa16(smb + OFF_CS + tid * 16, (const unsigned char*)g_c + tid * 16);
        CP_COMMIT();
        CP_WAIT0();
    }
    __syncthreads();

    // A fragments (fp16), 4 k-tiles
    const int r0 = warp * 16 + (lane >> 2);
    const int r1 = r0 + 8;
    uint32_t ax[4][4];
#pragma unroll
    for (int u = 0; u < 4; u++) {
        int kb = u * 16 + (lane & 3) * 2;
        ax[u][0] = h2(xs[r0 * DD + kb],     xs[r0 * DD + kb + 1]);
        ax[u][1] = h2(xs[r1 * DD + kb],     xs[r1 * DD + kb + 1]);
        ax[u][2] = h2(xs[r0 * DD + kb + 8], xs[r0 * DD + kb + 9]);
        ax[u][3] = h2(xs[r1 * DD + kb + 8], xs[r1 * DD + kb + 9]);
    }

    float v1a = -3.4e38f, v2a = -3.4e38f, v1b = -3.4e38f, v2b = -3.4e38f;
    int   i1a = 0, i1b = 0;

#pragma unroll 1
    for (int chunk = 0; chunk < 4; chunk++) {
        float dacc[16][4];
#pragma unroll
        for (int nt = 0; nt < 16; nt++)
#pragma unroll
            for (int j = 0; j < 4; j++) dacc[nt][j] = 0.f;

#pragma unroll
        for (int kt = 0; kt < 4; kt++) {
            const uint4* bp = bfr4 + ((kt * 32 + chunk * 8) * 32 + lane);
#pragma unroll
            for (int ntp = 0; ntp < 8; ntp++) {
                uint4 bb = bp[ntp * 32];
                hmma(dacc[2 * ntp],     ax[kt], bb.x, bb.y);
                hmma(dacc[2 * ntp + 1], ax[kt], bb.z, bb.w);
            }
        }

#pragma unroll
        for (int nt = 0; nt < 16; nt++) {
            int c0 = chunk * 128 + nt * 8 + (lane & 3) * 2;
            float cc0 = cs[c0], cc1 = cs[c0 + 1];
            t2(fmaf(2.f, dacc[nt][0], -cc0), c0,     v1a, i1a, v2a);
            t2(fmaf(2.f, dacc[nt][1], -cc1), c0 + 1, v1a, i1a, v2a);
            t2(fmaf(2.f, dacc[nt][2], -cc0), c0,     v1b, i1b, v2b);
            t2(fmaf(2.f, dacc[nt][3], -cc1), c0 + 1, v1b, i1b, v2b);
        }
    }

    // Merge across the 4 quad lanes (same rows, disjoint codes)
#pragma unroll
    for (int off = 1; off <= 2; off <<= 1) {
        float mv1 = __shfl_xor_sync(0xffffffffu, v1a, off);
        int   mi1 = __shfl_xor_sync(0xffffffffu, i1a, off);
        float mv2 = __shfl_xor_sync(0xffffffffu, v2a, off);
        t2(mv1, mi1, v1a, i1a, v2a);
        if (mv2 > v2a) v2a = mv2;
        mv1 = __shfl_xor_sync(0xffffffffu, v1b, off);
        mi1 = __shfl_xor_sync(0xffffffffu, i1b, off);
        mv2 = __shfl_xor_sync(0xffffffffu, v2b, off);
        t2(mv1, mi1, v1b, i1b, v2b);
        if (mv2 > v2b) v2b = mv2;
    }

    // Owner lanes: safe rows resolved now, near-ties flagged
    if ((lane & 3) == 0) {
        if (v1a - v2a >= EPS) s_idx[r0] = i1a;
        else { int p = atomicAdd(s_nflag, 1); s_frow[p] = r0; }
        if (v1b - v2b >= EPS) s_idx[r1] = i1b;
        else { int p = atomicAdd(s_nflag, 1); s_frow[p] = r1; }
    }
    __syncthreads();

    const int nf = *s_nflag;
    if (nf > 0) {
        // Two phases: codes [0,256) then [256,512); W slab d-major in smem.
#pragma unroll 1
        for (int p = 0; p < 2; p++) {
            __syncthreads();                     // prior readers done (BF reuse)
#pragma unroll
            for (int i = 0; i < 16; i++) {
                int idx = i * NT + tid;          // 4096 x 16B = 64 KB
                int d = idx >> 6, c4 = idx & 63;
                cpa16(smb + OFF_BF + (uint32_t)(d * 256 + c4 * 4) * 4,
                      w + (size_t)d * KK + p * 256 + c4 * 4);
            }
            CP_COMMIT();
            CP_WAIT0();
            __syncthreads();

            for (int e = warp; e < nf; e += 8) {
                int row = s_frow[e];
                float bv = -3.4e38f; int bi = 0;
#pragma unroll 1
                for (int j = 0; j < 8; j++) {
                    int cl = lane + 32 * j;      // ascending per lane
                    float s = 0.f;
#pragma unroll
                    for (int d = 0; d < DD; d++)
                        s = fmaf(xs[row * DD + d], wf[d * 256 + cl], s);
                    int c = p * 256 + cl;
                    float v = 2.f * s - cs[c];
                    if (v > bv) { bv = v; bi = c; }
                }
#pragma unroll
                for (int off = 16; off > 0; off >>= 1) {
                    float v2 = __shfl_xor_sync(0xffffffffu, bv, off);
                    int   c2 = __shfl_xor_sync(0xffffffffu, bi, off);
                    if (v2 > bv || (v2 == bv && c2 < bi)) { bv = v2; bi = c2; }
                }
                if (lane == 0) {
                    if (p == 0) { s_fbv[e] = bv; s_fbi[e] = bi; }
                    else {
                        float v0 = s_fbv[e]; int i0 = s_fbi[e];
                        s_idx[row] = (bv > v0 || (bv == v0 && bi < i0)) ? bi : i0;
                    }
                }
            }
        }
    }
    __syncthreads();

    // Index + histogram outputs
    if (lane < 16) {
        int rr = warp * 16 + lane;
        int bi = s_idx[rr];
        out_idx[rowBase + rr] = (float)bi;
        atomicAdd(&g_hist[bi], 1u);
    }

    // Gather/ST/SSE epilogue: warp handles its 16 rows, lanes = dims
    float sse = 0.f;
#pragma unroll 1
    for (int i = 0; i < 16; i++) {
        int rowl = warp * 16 + i;
        int bir  = s_idx[rowl];                  // broadcast LDS
        float2 q  = *(const float2*)(g_wt + (size_t)bir * DD + lane * 2);
        float2 xv = *(const float2*)(xs + rowl * DD + lane * 2);
        float d0 = q.x - xv.x, d1 = q.y - xv.y;
        float2 st;
        st.x = xv.x + d0;                        // x + (q - x), reference rounding
        st.y = xv.y + d1;
        *(float2*)(out_q + (size_t)(rowBase + rowl) * DD + lane * 2) = st;
        sse += d0 * d0 + d1 * d1;
    }
#pragma unroll
    for (int off = 16; off > 0; off >>= 1)
        sse += __shfl_xor_sync(0xffffffffu, sse, off);
    if (lane == 0) atomicAdd(&g_sse, (double)sse);
}

// ---------------------------------------------------------------------------
// Finalize: loss + perplexity
// ---------------------------------------------------------------------------
__global__ void vq_finalize(float* __restrict__ out_tail) {
    __shared__ float red[KK];
    int t = threadIdx.x;
    float p = (float)g_hist[t] / (float)NVEC;
    red[t] = -p * logf(p + 1e-10f);
    __syncthreads();
#pragma unroll
    for (int s = KK / 2; s > 0; s >>= 1) {
        if (t < s) red[t] += red[t + s];
        __syncthreads();
    }
    if (t == 0) {
        float m = (float)(g_sse / (double)((size_t)NVEC * DD));
        out_tail[0] = m + 0.25f * m;
        out_tail[1] = expf(red[0]);
    }
}

// ---------------------------------------------------------------------------
extern "C" void kernel_launch(void* const* d_in, const int* in_sizes, int n_in,
                              void* d_out, int out_size) {
    const float* x = (const float*)d_in[0];
    const float* w = (const float*)d_in[1];
    float* out = (float*)d_out;

    const int N = in_sizes[0] / DD;            // 65536
    const size_t ND = (size_t)N * DD;

    float* out_q    = out;
    float* out_tail = out + ND;                // loss, perplexity
    float* out_idx  = out + ND + 2;

    cudaFuncSetAttribute(vq_main, cudaFuncAttributeMaxDynamicSharedMemorySize,
                         SMEM_TOTAL);

    vq_prep<<<16, 256>>>(w);
    vq_main<<<N / ROWS, NT, SMEM_TOTAL>>>(x, w, out_q, out_idx);
    vq_finalize<<<1, KK>>>(out_tail);
}